// round 8
// baseline (speedup 1.0000x reference)
#include <cuda_runtime.h>
#include <cstdint>

#define DD 128
#define ROWS_ITER 256        // rows per CTA iteration (32 per warp)
#define ITERS 4              // iterations per CTA -> 1024 rows/CTA
#define NTHREADS 256

// ---- smem byte offsets ----
#define SM_B1HI 0            // R hi, fragment-packed
#define SM_B1LO 65536        // R lo
#define SM_ZI   131072       // indices: 256 rows x 132 bytes
#define SM_NRM  164864       // 256 f32
#define SM_INV  165888       // 256 f32
#define SM_SCL  166912       // 128 f32
#define SM_ISCL 167424       // 128 f32
#define SMEM_BYTES 167936

__device__ __forceinline__ uint32_t tf32u(float x) {
    uint32_t r;
    asm("cvt.rna.tf32.f32 %0, %1;" : "=r"(r) : "f"(x));
    return r;
}

__device__ __forceinline__ void mma8(float d[4], const uint32_t a[4],
                                     uint32_t b0, uint32_t b1) {
    asm volatile(
        "mma.sync.aligned.m16n8k8.row.col.f32.tf32.tf32.f32 "
        "{%0,%1,%2,%3}, {%4,%5,%6,%7}, {%8,%9}, {%0,%1,%2,%3};"
        : "+f"(d[0]), "+f"(d[1]), "+f"(d[2]), "+f"(d[3])
        : "r"(a[0]), "r"(a[1]), "r"(a[2]), "r"(a[3]), "r"(b0), "r"(b1));
}

__device__ __forceinline__ void split4(const float f[4], uint32_t h[4], uint32_t l[4]) {
    #pragma unroll
    for (int i = 0; i < 4; ++i) {
        h[i] = tf32u(f[i]);
        l[i] = tf32u(f[i] - __uint_as_float(h[i]));
    }
}

extern "C" __global__ void __launch_bounds__(NTHREADS, 1)
rotadapt_mma_kernel(const float* __restrict__ k,
                    const float* __restrict__ rot,
                    const float* __restrict__ scales,
                    const float* __restrict__ cent,
                    float* __restrict__ out)
{
    extern __shared__ char sb[];
    float* sclp  = (float*)(sb + SM_SCL);
    float* isclp = (float*)(sb + SM_ISCL);
    float* nrmp  = (float*)(sb + SM_NRM);
    float* invp  = (float*)(sb + SM_INV);

    const int tid  = threadIdx.x;
    const int lane = tid & 31, w = tid >> 5;
    const int g = lane >> 2, t = lane & 3;
    const int rA = 32 * w + g;       // tile0 rows rA, rA+8
    const int rB = rA + 16;          // tile1 rows rB, rB+8

    // ---- prologue: pack R into hi/lo fragment layout ----
    for (int idx = tid; idx < DD * DD; idx += NTHREADS) {
        int j = idx >> 7, i = idx & 127;
        float v = rot[idx];
        uint32_t hu = tf32u(v);
        uint32_t lu = tf32u(v - __uint_as_float(hu));
        int fi = (((i >> 3) * 16 + (j >> 3)) * 32 + (j & 7) * 4 + (i & 3)) * 2
                 + ((i >> 2) & 1);
        ((uint32_t*)(sb + SM_B1HI))[fi] = hu;
        ((uint32_t*)(sb + SM_B1LO))[fi] = lu;
    }
    if (tid < DD) {
        float s = scales[tid];
        sclp[tid]  = s;
        isclp[tid] = 1.0f / fmaxf(s, 1e-6f);
    }

    float bn[7];
    #pragma unroll
    for (int q = 0; q < 7; ++q) bn[q] = 0.5f * (cent[q] + cent[q + 1]);
    const float ccv = cent[lane & 7];

    __syncthreads();   // the ONLY block barrier: B tables + scales ready

    const float2* bh2 = (const float2*)(sb + SM_B1HI);
    const float2* bl2 = (const float2*)(sb + SM_B1LO);
    const float*  bhf = (const float*)(sb + SM_B1HI);
    char* zi = sb + SM_ZI;

    const long ctabase = (long)blockIdx.x * (ROWS_ITER * ITERS);

    for (int tt = 0; tt < ITERS; ++tt) {
        const long rowbase = ctabase + (long)tt * ROWS_ITER;

        // ---- phase A: row norms (warp-private rows; no block sync) ----
        {
            const int sub = lane >> 3, c8 = lane & 7;
            #pragma unroll
            for (int p = 0; p < 8; ++p) {
                int row = 32 * w + 4 * p + sub;
                const float4* kp = (const float4*)(k + (rowbase + row) * (long)DD);
                float ssq = 0.0f;
                #pragma unroll
                for (int ci = 0; ci < 4; ++ci) {
                    float4 v = kp[ci * 8 + c8];
                    ssq += v.x * v.x + v.y * v.y + v.z * v.z + v.w * v.w;
                }
                ssq += __shfl_xor_sync(0xffffffffu, ssq, 1);
                ssq += __shfl_xor_sync(0xffffffffu, ssq, 2);
                ssq += __shfl_xor_sync(0xffffffffu, ssq, 4);
                if (c8 == 0) {
                    float nr = sqrtf(ssq);
                    nrmp[row] = nr;
                    invp[row] = 1.0f / (nr + 1e-10f);
                }
            }
        }
        __syncwarp();   // also orders ZI reuse: prev GEMM2 reads < this epi1 writes
        float invA0 = invp[rA],      invA1 = invp[rA + 8];
        float invB0 = invp[rB],      invB1 = invp[rB + 8];
        float nrmA0 = nrmp[rA],      nrmA1 = nrmp[rA + 8];
        float nrmB0 = nrmp[rB],      nrmB1 = nrmp[rB + 8];

        // ---- GEMM1 (3-pass tf32), pass-major MMA order (acc reuse dist = 16) ----
        float acc[2][16][4];
        #pragma unroll
        for (int i = 0; i < 2; ++i)
            #pragma unroll
            for (int nt = 0; nt < 16; ++nt)
                #pragma unroll
                for (int p = 0; p < 4; ++p) acc[i][nt][p] = 0.0f;

        {
            const float* kA0 = k + (rowbase + rA) * (long)DD;
            const float* kA1 = kA0 + 8 * DD;
            const float* kB0 = kA0 + 16 * DD;
            const float* kB1 = kA0 + 24 * DD;

            #pragma unroll 2
            for (int ks = 0; ks < 16; ++ks) {
                int o = 8 * ks + t;
                float fA[4] = { kA0[o] * invA0,     kA1[o] * invA1,
                                kA0[o + 4] * invA0, kA1[o + 4] * invA1 };
                float fB[4] = { kB0[o] * invB0,     kB1[o] * invB1,
                                kB0[o + 4] * invB0, kB1[o + 4] * invB1 };
                uint32_t ahA[4], alA[4], ahB[4], alB[4];
                split4(fA, ahA, alA);
                split4(fB, ahB, alB);

                #pragma unroll
                for (int grp = 0; grp < 2; ++grp) {
                    const int n0 = grp * 8;
                    uint32_t bh0[8], bh1[8], bl0[8], bl1[8];
                    #pragma unroll
                    for (int j = 0; j < 8; ++j) {
                        int fi = (ks * 16 + n0 + j) * 32 + lane;
                        float2 bh = bh2[fi];
                        float2 bl = bl2[fi];
                        bh0[j] = __float_as_uint(bh.x);
                        bh1[j] = __float_as_uint(bh.y);
                        bl0[j] = __float_as_uint(bl.x);
                        bl1[j] = __float_as_uint(bl.y);
                    }
                    // pass-major: per-acc order is ah*bh, al*bh, ah*bl (unchanged)
                    #pragma unroll
                    for (int j = 0; j < 8; ++j) mma8(acc[0][n0 + j], ahA, bh0[j], bh1[j]);
                    #pragma unroll
                    for (int j = 0; j < 8; ++j) mma8(acc[1][n0 + j], ahB, bh0[j], bh1[j]);
                    #pragma unroll
                    for (int j = 0; j < 8; ++j) mma8(acc[0][n0 + j], alA, bh0[j], bh1[j]);
                    #pragma unroll
                    for (int j = 0; j < 8; ++j) mma8(acc[1][n0 + j], alB, bh0[j], bh1[j]);
                    #pragma unroll
                    for (int j = 0; j < 8; ++j) mma8(acc[0][n0 + j], ahA, bl0[j], bl1[j]);
                    #pragma unroll
                    for (int j = 0; j < 8; ++j) mma8(acc[1][n0 + j], ahB, bl0[j], bl1[j]);
                }
            }
        }

        // ---- prefetch next iteration's k toward L2 ----
        if (tt + 1 < ITERS) {
            const char* np = (const char*)(k + (rowbase + ROWS_ITER) * (long)DD);
            #pragma unroll
            for (int pf = 0; pf < 4; ++pf)
                asm volatile("prefetch.global.L2 [%0];"
                             :: "l"(np + (pf * NTHREADS + tid) * 128));
        }

        // ---- epilogue 1: scale -> bucketize -> 8-bit indices to smem ----
        {
            const float2* scl2 = (const float2*)(sb + SM_SCL);
            #pragma unroll
            for (int i = 0; i < 2; ++i) {
                int ra = rA + 16 * i, rb = ra + 8;
                #pragma unroll
                for (int nt = 0; nt < 16; ++nt) {
                    float2 sc = scl2[(8 * nt + 2 * t) >> 1];
                    float f0 = acc[i][nt][0] * sc.x, f1 = acc[i][nt][1] * sc.y;
                    float f2 = acc[i][nt][2] * sc.x, f3 = acc[i][nt][3] * sc.y;
                    int i0 = 0, i1 = 0, i2 = 0, i3 = 0;
                    #pragma unroll
                    for (int q = 0; q < 7; ++q) {
                        i0 += (f0 > bn[q]); i1 += (f1 > bn[q]);
                        i2 += (f2 > bn[q]); i3 += (f3 > bn[q]);
                    }
                    *(uint16_t*)(zi + ra * 132 + 8 * nt + 2 * t) = (uint16_t)(i0 | (i1 << 8));
                    *(uint16_t*)(zi + rb * 132 + 8 * nt + 2 * t) = (uint16_t)(i2 | (i3 << 8));
                }
            }
        }
        __syncwarp();

        // ---- GEMM2 (2-pass tf32), pass-major MMA order ----
        float acc2[2][16][4];
        #pragma unroll
        for (int i = 0; i < 2; ++i)
            #pragma unroll
            for (int nt = 0; nt < 16; ++nt)
                #pragma unroll
                for (int p = 0; p < 4; ++p) acc2[i][nt][p] = 0.0f;

        {
            #pragma unroll 2
            for (int ks = 0; ks < 16; ++ks) {
                float is0 = isclp[8 * ks + t], is1 = isclp[8 * ks + t + 4];
                int sh = 8 * t;
                uint32_t zhA[4], zlA[4], zhB[4], zlB[4];
                {
                    uint32_t wa = *(const uint32_t*)(zi + rA * 132 + 8 * ks);
                    uint32_t wb = *(const uint32_t*)(zi + rA * 132 + 8 * ks + 4);
                    uint32_t wc = *(const uint32_t*)(zi + (rA + 8) * 132 + 8 * ks);
                    uint32_t wd = *(const uint32_t*)(zi + (rA + 8) * 132 + 8 * ks + 4);
                    float fz[4] = {
                        __shfl_sync(0xffffffffu, ccv, (wa >> sh) & 0xff) * is0,
                        __shfl_sync(0xffffffffu, ccv, (wc >> sh) & 0xff) * is0,
                        __shfl_sync(0xffffffffu, ccv, (wb >> sh) & 0xff) * is1,
                        __shfl_sync(0xffffffffu, ccv, (wd >> sh) & 0xff) * is1 };
                    split4(fz, zhA, zlA);
                }
                {
                    uint32_t wa = *(const uint32_t*)(zi + rB * 132 + 8 * ks);
                    uint32_t wb = *(const uint32_t*)(zi + rB * 132 + 8 * ks + 4);
                    uint32_t wc = *(const uint32_t*)(zi + (rB + 8) * 132 + 8 * ks);
                    uint32_t wd = *(const uint32_t*)(zi + (rB + 8) * 132 + 8 * ks + 4);
                    float fz[4] = {
                        __shfl_sync(0xffffffffu, ccv, (wa >> sh) & 0xff) * is0,
                        __shfl_sync(0xffffffffu, ccv, (wc >> sh) & 0xff) * is0,
                        __shfl_sync(0xffffffffu, ccv, (wb >> sh) & 0xff) * is1,
                        __shfl_sync(0xffffffffu, ccv, (wd >> sh) & 0xff) * is1 };
                    split4(fz, zhB, zlB);
                }

                #pragma unroll
                for (int grp = 0; grp < 2; ++grp) {
                    const int n0 = grp * 8;
                    uint32_t b0[8], b1[8];
                    #pragma unroll
                    for (int j = 0; j < 8; ++j) {
                        int base = (((n0 + j) * 16 + ks) * 32 + t * 4 + (g & 3)) * 2 + (g >> 2);
                        b0[j] = __float_as_uint(bhf[base]);
                        b1[j] = __float_as_uint(bhf[base + 32]);
                    }
                    // pass-major: per-acc order is zh, zl (unchanged)
                    #pragma unroll
                    for (int j = 0; j < 8; ++j) mma8(acc2[0][n0 + j], zhA, b0[j], b1[j]);
                    #pragma unroll
                    for (int j = 0; j < 8; ++j) mma8(acc2[1][n0 + j], zhB, b0[j], b1[j]);
                    #pragma unroll
                    for (int j = 0; j < 8; ++j) mma8(acc2[0][n0 + j], zlA, b0[j], b1[j]);
                    #pragma unroll
                    for (int j = 0; j < 8; ++j) mma8(acc2[1][n0 + j], zlB, b0[j], b1[j]);
                }
            }
        }

        // ---- epilogue 2: x norm, store ----
        #pragma unroll
        for (int i = 0; i < 2; ++i) {
            float n0 = i ? nrmB0 : nrmA0;
            float n1 = i ? nrmB1 : nrmA1;
            float* o0 = out + (rowbase + rA + 16 * i) * (long)DD;
            float* o1 = o0 + 8 * DD;
            #pragma unroll
            for (int nt = 0; nt < 16; ++nt) {
                int c = 8 * nt + 2 * t;
                *(float2*)(o0 + c) = make_float2(acc2[i][nt][0] * n0, acc2[i][nt][1] * n0);
                *(float2*)(o1 + c) = make_float2(acc2[i][nt][2] * n1, acc2[i][nt][3] * n1);
            }
        }
    }
}

extern "C" void kernel_launch(void* const* d_in, const int* in_sizes, int n_in,
                              void* d_out, int out_size) {
    const float* k      = (const float*)d_in[0];
    const float* rot    = (const float*)d_in[1];
    const float* scales = (const float*)d_in[2];
    const float* cent   = (const float*)d_in[3];
    float* out = (float*)d_out;

    int nrows = in_sizes[0] / DD;
    int nblocks = nrows / (ROWS_ITER * ITERS);   // 1048576 / 1024 = 1024

    cudaFuncSetAttribute(rotadapt_mma_kernel,
                         cudaFuncAttributeMaxDynamicSharedMemorySize, SMEM_BYTES);
    rotadapt_mma_kernel<<<nblocks, NTHREADS, SMEM_BYTES>>>(k, rot, scales, cent, out);
}

// round 9
// speedup vs baseline: 1.2145x; 1.2145x over previous
#include <cuda_runtime.h>
#include <cstdint>

#define DD 128
#define ROWS_ITER 256        // rows per CTA iteration (16 per warp)
#define ITERS 4              // iterations per CTA -> 1024 rows/CTA
#define NTHREADS 512

// ---- smem byte offsets ----
#define SM_B1HI 0            // R hi, fragment-packed
#define SM_B1LO 65536        // R lo
#define SM_ZI   131072       // indices: 256 rows x 132 bytes
#define SM_NRM  164864       // 256 f32
#define SM_INV  165888       // 256 f32
#define SM_SCL  166912       // 128 f32
#define SM_ISCL 167424       // 128 f32
#define SMEM_BYTES 167936

__device__ __forceinline__ uint32_t tf32u(float x) {
    uint32_t r;
    asm("cvt.rna.tf32.f32 %0, %1;" : "=r"(r) : "f"(x));
    return r;
}

__device__ __forceinline__ void mma8(float d[4], const uint32_t a[4],
                                     uint32_t b0, uint32_t b1) {
    asm volatile(
        "mma.sync.aligned.m16n8k8.row.col.f32.tf32.tf32.f32 "
        "{%0,%1,%2,%3}, {%4,%5,%6,%7}, {%8,%9}, {%0,%1,%2,%3};"
        : "+f"(d[0]), "+f"(d[1]), "+f"(d[2]), "+f"(d[3])
        : "r"(a[0]), "r"(a[1]), "r"(a[2]), "r"(a[3]), "r"(b0), "r"(b1));
}

__device__ __forceinline__ void split4(const float f[4], uint32_t h[4], uint32_t l[4]) {
    #pragma unroll
    for (int i = 0; i < 4; ++i) {
        h[i] = tf32u(f[i]);
        l[i] = tf32u(f[i] - __uint_as_float(h[i]));
    }
}

extern "C" __global__ void __launch_bounds__(NTHREADS, 1)
rotadapt_mma_kernel(const float* __restrict__ k,
                    const float* __restrict__ rot,
                    const float* __restrict__ scales,
                    const float* __restrict__ cent,
                    float* __restrict__ out)
{
    extern __shared__ char sb[];
    float* sclp  = (float*)(sb + SM_SCL);
    float* isclp = (float*)(sb + SM_ISCL);
    float* nrmp  = (float*)(sb + SM_NRM);
    float* invp  = (float*)(sb + SM_INV);

    const int tid  = threadIdx.x;
    const int lane = tid & 31, w = tid >> 5;      // 16 warps
    const int g = lane >> 2, t = lane & 3;
    const int rA = 16 * w + g;                    // warp owns rows [16w, 16w+16)

    // ---- prologue: pack R into hi/lo fragment layout ----
    for (int idx = tid; idx < DD * DD; idx += NTHREADS) {
        int j = idx >> 7, i = idx & 127;
        float v = rot[idx];
        uint32_t hu = tf32u(v);
        uint32_t lu = tf32u(v - __uint_as_float(hu));
        int fi = (((i >> 3) * 16 + (j >> 3)) * 32 + (j & 7) * 4 + (i & 3)) * 2
                 + ((i >> 2) & 1);
        ((uint32_t*)(sb + SM_B1HI))[fi] = hu;
        ((uint32_t*)(sb + SM_B1LO))[fi] = lu;
    }
    if (tid < DD) {
        float s = scales[tid];
        sclp[tid]  = s;
        isclp[tid] = 1.0f / fmaxf(s, 1e-6f);
    }

    float bn[7];
    #pragma unroll
    for (int q = 0; q < 7; ++q) bn[q] = 0.5f * (cent[q] + cent[q + 1]);
    const float ccv = cent[lane & 7];

    __syncthreads();   // the ONLY block barrier: B tables + scales ready

    const float2* bh2 = (const float2*)(sb + SM_B1HI);
    const float2* bl2 = (const float2*)(sb + SM_B1LO);
    const float*  bhf = (const float*)(sb + SM_B1HI);
    char* zi = sb + SM_ZI;

    const long ctabase = (long)blockIdx.x * (ROWS_ITER * ITERS);

    for (int tt = 0; tt < ITERS; ++tt) {
        const long rowbase = ctabase + (long)tt * ROWS_ITER;

        // ---- phase A: row norms (warp-private rows; no block sync) ----
        {
            const int sub = lane >> 3, c8 = lane & 7;
            #pragma unroll
            for (int p = 0; p < 4; ++p) {
                int row = 16 * w + 4 * p + sub;
                const float4* kp = (const float4*)(k + (rowbase + row) * (long)DD);
                float ssq = 0.0f;
                #pragma unroll
                for (int ci = 0; ci < 4; ++ci) {
                    float4 v = kp[ci * 8 + c8];
                    ssq += v.x * v.x + v.y * v.y + v.z * v.z + v.w * v.w;
                }
                ssq += __shfl_xor_sync(0xffffffffu, ssq, 1);
                ssq += __shfl_xor_sync(0xffffffffu, ssq, 2);
                ssq += __shfl_xor_sync(0xffffffffu, ssq, 4);
                if (c8 == 0) {
                    float nr = sqrtf(ssq);
                    nrmp[row] = nr;
                    invp[row] = 1.0f / (nr + 1e-10f);
                }
            }
        }
        __syncwarp();   // also orders ZI reuse: prev GEMM2 reads < this epi1 writes
        const float inv0 = invp[rA], inv1 = invp[rA + 8];
        const float nrm0 = nrmp[rA], nrm1 = nrmp[rA + 8];

        // ---- GEMM1 (3-pass tf32): one m16 row-tile, acc reused for GEMM2 later ----
        float acc[16][4];
        #pragma unroll
        for (int nt = 0; nt < 16; ++nt)
            #pragma unroll
            for (int p = 0; p < 4; ++p) acc[nt][p] = 0.0f;

        {
            const float* k0 = k + (rowbase + rA) * (long)DD;
            const float* k1 = k0 + 8 * DD;

            #pragma unroll 2
            for (int ks = 0; ks < 16; ++ks) {
                int o = 8 * ks + t;
                float fA[4] = { k0[o] * inv0,     k1[o] * inv1,
                                k0[o + 4] * inv0, k1[o + 4] * inv1 };
                uint32_t ah[4], al[4];
                split4(fA, ah, al);

                float2 bhb[2][4], blb[2][4];
                #pragma unroll
                for (int j = 0; j < 4; ++j) {
                    int fi = (ks * 16 + j) * 32 + lane;
                    bhb[0][j] = bh2[fi];
                    blb[0][j] = bl2[fi];
                }
                #pragma unroll
                for (int grp = 0; grp < 4; ++grp) {
                    const int cur = grp & 1, nxt = cur ^ 1;
                    if (grp < 3) {
                        #pragma unroll
                        for (int j = 0; j < 4; ++j) {
                            int fi = (ks * 16 + (grp + 1) * 4 + j) * 32 + lane;
                            bhb[nxt][j] = bh2[fi];
                            blb[nxt][j] = bl2[fi];
                        }
                    }
                    #pragma unroll
                    for (int j = 0; j < 4; ++j) {
                        int nt = grp * 4 + j;
                        uint32_t bh0 = __float_as_uint(bhb[cur][j].x);
                        uint32_t bh1 = __float_as_uint(bhb[cur][j].y);
                        uint32_t bl0 = __float_as_uint(blb[cur][j].x);
                        uint32_t bl1 = __float_as_uint(blb[cur][j].y);
                        mma8(acc[nt], ah, bh0, bh1);
                        mma8(acc[nt], al, bh0, bh1);
                        mma8(acc[nt], ah, bl0, bl1);
                    }
                }
            }
        }

        // ---- prefetch next iteration's k toward L2 ----
        if (tt + 1 < ITERS) {
            const char* np = (const char*)(k + (rowbase + ROWS_ITER) * (long)DD);
            #pragma unroll
            for (int pf = 0; pf < 2; ++pf)
                asm volatile("prefetch.global.L2 [%0];"
                             :: "l"(np + (pf * NTHREADS + tid) * 128));
        }

        // ---- epilogue 1: scale -> bucketize -> 8-bit indices to smem ----
        {
            const float2* scl2 = (const float2*)(sb + SM_SCL);
            #pragma unroll
            for (int nt = 0; nt < 16; ++nt) {
                float2 sc = scl2[(8 * nt + 2 * t) >> 1];
                float f0 = acc[nt][0] * sc.x, f1 = acc[nt][1] * sc.y;
                float f2 = acc[nt][2] * sc.x, f3 = acc[nt][3] * sc.y;
                int i0 = 0, i1 = 0, i2 = 0, i3 = 0;
                #pragma unroll
                for (int q = 0; q < 7; ++q) {
                    i0 += (f0 > bn[q]); i1 += (f1 > bn[q]);
                    i2 += (f2 > bn[q]); i3 += (f3 > bn[q]);
                }
                *(uint16_t*)(zi + rA * 132 + 8 * nt + 2 * t)       = (uint16_t)(i0 | (i1 << 8));
                *(uint16_t*)(zi + (rA + 8) * 132 + 8 * nt + 2 * t) = (uint16_t)(i2 | (i3 << 8));
            }
        }
        __syncwarp();

        // ---- GEMM2 (2-pass tf32): reuse acc registers ----
        #pragma unroll
        for (int nt = 0; nt < 16; ++nt)
            #pragma unroll
            for (int p = 0; p < 4; ++p) acc[nt][p] = 0.0f;

        {
            #pragma unroll 2
            for (int ks = 0; ks < 16; ++ks) {
                float is0 = isclp[8 * ks + t], is1 = isclp[8 * ks + t + 4];
                int sh = 8 * t;
                uint32_t zh[4], zl[4];
                {
                    uint32_t wa = *(const uint32_t*)(zi + rA * 132 + 8 * ks);
                    uint32_t wb = *(const uint32_t*)(zi + rA * 132 + 8 * ks + 4);
                    uint32_t wc = *(const uint32_t*)(zi + (rA + 8) * 132 + 8 * ks);
                    uint32_t wd = *(const uint32_t*)(zi + (rA + 8) * 132 + 8 * ks + 4);
                    float fz[4] = {
                        __shfl_sync(0xffffffffu, ccv, (wa >> sh) & 0xff) * is0,
                        __shfl_sync(0xffffffffu, ccv, (wc >> sh) & 0xff) * is0,
                        __shfl_sync(0xffffffffu, ccv, (wb >> sh) & 0xff) * is1,
                        __shfl_sync(0xffffffffu, ccv, (wd >> sh) & 0xff) * is1 };
                    split4(fz, zh, zl);
                }

                float b0b[2][4], b1b[2][4];
                #pragma unroll
                for (int j = 0; j < 4; ++j) {
                    int base = ((j * 16 + ks) * 32 + t * 4 + (g & 3)) * 2 + (g >> 2);
                    b0b[0][j] = bhf[base];
                    b1b[0][j] = bhf[base + 32];
                }
                #pragma unroll
                for (int grp = 0; grp < 4; ++grp) {
                    const int cur = grp & 1, nxt = cur ^ 1;
                    if (grp < 3) {
                        #pragma unroll
                        for (int j = 0; j < 4; ++j) {
                            int nt2 = (grp + 1) * 4 + j;
                            int base = ((nt2 * 16 + ks) * 32 + t * 4 + (g & 3)) * 2 + (g >> 2);
                            b0b[nxt][j] = bhf[base];
                            b1b[nxt][j] = bhf[base + 32];
                        }
                    }
                    #pragma unroll
                    for (int j = 0; j < 4; ++j) {
                        int nt = grp * 4 + j;
                        uint32_t b0 = __float_as_uint(b0b[cur][j]);
                        uint32_t b1 = __float_as_uint(b1b[cur][j]);
                        mma8(acc[nt], zh, b0, b1);
                        mma8(acc[nt], zl, b0, b1);
                    }
                }
            }
        }

        // ---- epilogue 2: x norm, store ----
        {
            float* o0 = out + (rowbase + rA) * (long)DD;
            float* o1 = o0 + 8 * DD;
            #pragma unroll
            for (int nt = 0; nt < 16; ++nt) {
                int c = 8 * nt + 2 * t;
                *(float2*)(o0 + c) = make_float2(acc[nt][0] * nrm0, acc[nt][1] * nrm0);
                *(float2*)(o1 + c) = make_float2(acc[nt][2] * nrm1, acc[nt][3] * nrm1);
            }
        }
    }
}

extern "C" void kernel_launch(void* const* d_in, const int* in_sizes, int n_in,
                              void* d_out, int out_size) {
    const float* k      = (const float*)d_in[0];
    const float* rot    = (const float*)d_in[1];
    const float* scales = (const float*)d_in[2];
    const float* cent   = (const float*)d_in[3];
    float* out = (float*)d_out;

    int nrows = in_sizes[0] / DD;
    int nblocks = nrows / (ROWS_ITER * ITERS);   // 1048576 / 1024 = 1024

    cudaFuncSetAttribute(rotadapt_mma_kernel,
                         cudaFuncAttributeMaxDynamicSharedMemorySize, SMEM_BYTES);
    rotadapt_mma_kernel<<<nblocks, NTHREADS, SMEM_BYTES>>>(k, rot, scales, cent, out);
}